// round 6
// baseline (speedup 1.0000x reference)
#include <cuda_runtime.h>
#include <math.h>

// PQLayer forward, fully fused (R5, resubmitted after infra failure):
//   per (b,m): k* = argmax_k <x[b,m*8:+8], C[m,k,:]>
//   codes[b,m,:] = one_hot(k*)   (exact forward value of straight-through)
//   xhat[b,m*8:+8] = C[m,k*,:]
//
// R5 vs R4: zero-stores hoisted ahead of compute; x staged DUPLICATED in smem
// so f32x2 operands load directly (no pack MOVs); value-only fmax tree +
// single redux.max + ballot ownership (no index SELs, no second redux);
// owner's codeword comes from an smem copy of C[m] (29cyc LDS, not 234cyc LDG).
// Dot summation order identical to R3/R4 -> bit-identical argmax.

#define Bn    16384
#define FEAT  512
#define Mn    64
#define Kn    256
#define Dn    8
#define WARPS 8
#define RPW   32
#define TILEB (WARPS * RPW)   // 256 rows per block

typedef unsigned long long u64;
typedef unsigned int u32;

__device__ __forceinline__ u64 pack2(float lo, float hi) {
    u64 r; asm("mov.b64 %0, {%1,%2};" : "=l"(r) : "f"(lo), "f"(hi)); return r;
}
__device__ __forceinline__ void unpack2(u64 v, float& lo, float& hi) {
    asm("mov.b64 {%0,%1}, %2;" : "=f"(lo), "=f"(hi) : "l"(v));
}
__device__ __forceinline__ u64 fma2(u64 a, u64 b, u64 c) {
    u64 d; asm("fma.rn.f32x2 %0, %1, %2, %3;" : "=l"(d) : "l"(a), "l"(b), "l"(c)); return d;
}
__device__ __forceinline__ u64 mul2(u64 a, u64 b) {
    u64 d; asm("mul.rn.f32x2 %0, %1, %2;" : "=l"(d) : "l"(a), "l"(b)); return d;
}
__device__ __forceinline__ void stg256_zero(void* p) {
    u32 z = 0u;
    asm volatile("st.global.v8.b32 [%0], {%1,%1,%1,%1,%1,%1,%1,%1};"
                 :: "l"(p), "r"(z) : "memory");
}
__device__ __forceinline__ void stg256f(void* p, float4 a, float4 b) {
    asm volatile("st.global.v8.b32 [%0], {%1,%2,%3,%4,%5,%6,%7,%8};"
                 :: "l"(p),
                    "r"(__float_as_uint(a.x)), "r"(__float_as_uint(a.y)),
                    "r"(__float_as_uint(a.z)), "r"(__float_as_uint(a.w)),
                    "r"(__float_as_uint(b.x)), "r"(__float_as_uint(b.y)),
                    "r"(__float_as_uint(b.z)), "r"(__float_as_uint(b.w))
                 : "memory");
}

// Dots for one row; x comes pre-duplicated from smem. f[i] = dot with
// codeword lane*8+i. Summation order identical to R3/R4.
__device__ __forceinline__ void row_dots(const float* __restrict__ xdup,
                                         const u64 cc[4][8], float f[8])
{
    const ulonglong2* xp = reinterpret_cast<const ulonglong2*>(xdup);
    const ulonglong2 q0 = xp[0], q1 = xp[1], q2 = xp[2], q3 = xp[3];
    const u64 xx[8] = { q0.x, q0.y, q1.x, q1.y, q2.x, q2.y, q3.x, q3.y };
#pragma unroll
    for (int p = 0; p < 4; p++) {
        u64 acc = mul2(cc[p][0], xx[0]);
#pragma unroll
        for (int d = 1; d < 8; d++) acc = fma2(cc[p][d], xx[d], acc);
        unpack2(acc, f[2 * p], f[2 * p + 1]);
    }
}

__device__ __forceinline__ float max8(const float f[8])
{
    return fmaxf(fmaxf(fmaxf(f[0], f[1]), fmaxf(f[2], f[3])),
                 fmaxf(fmaxf(f[4], f[5]), fmaxf(f[6], f[7])));
}

// Order-preserving uint map of a float (total order matching >).
__device__ __forceinline__ u32 ordmap(float v)
{
    u32 o = __float_as_uint(v);
    return (o & 0x80000000u) ? ~o : (o | 0x80000000u);
}

// Owner lane: patch the 1.0 into its own codes slice and write xhat from the
// smem codebook tile. First-occurrence: lowest local j with f[j]==best
// (fmaxf result is bit-equal to the max element).
__device__ __forceinline__ void emit_owner(const float f[8], float best,
                                           float* cp, const float* Cs,
                                           int lane, float* xo)
{
    int j = 7;
#pragma unroll
    for (int i = 6; i >= 0; i--) if (f[i] == best) j = i;
    cp[j] = 1.0f;                       // same thread, after the zero store
    const int k = lane * 8 + j;
    const float4* cw = reinterpret_cast<const float4*>(Cs + k * Dn);
    stg256f(xo, cw[0], cw[1]);
}

__global__ __launch_bounds__(TILEB, 2)
void pq_fused_kernel(const float* __restrict__ x,
                     const float* __restrict__ C,
                     float* __restrict__ xhat,
                     float* __restrict__ codes)
{
    __shared__ float xsd[TILEB * 16];   // 16 KB: x, each value duplicated
    __shared__ float Cs[Kn * Dn];       // 8 KB: C[m] tile

    const int m     = blockIdx.x;
    const int warp  = threadIdx.x >> 5;
    const int lane  = threadIdx.x & 31;
    const int tid   = threadIdx.x;
    const int btile = blockIdx.y * TILEB;

    // ---- Stage x tile, duplicated: smem u64 d of row = (x_d, x_d).
#pragma unroll
    for (int pass = 0; pass < 2; pass++) {
        const int fi   = pass * TILEB + tid;     // float4 id, 0..511
        const int row  = fi >> 1;
        const int half = fi & 1;
        const float4 v = __ldg(reinterpret_cast<const float4*>(
            x + (size_t)(btile + row) * FEAT + m * Dn + half * 4));
        float4* dst = reinterpret_cast<float4*>(xsd + row * 16 + half * 8);
        dst[0] = make_float4(v.x, v.x, v.y, v.y);
        dst[1] = make_float4(v.z, v.z, v.w, v.w);
    }
    // ---- Stage C[m] tile (2048 floats, coalesced).
#pragma unroll
    for (int pass = 0; pass < 2; pass++) {
        const int fi = pass * TILEB + tid;
        reinterpret_cast<float4*>(Cs)[fi] = __ldg(
            reinterpret_cast<const float4*>(C + (size_t)m * Kn * Dn) + fi);
    }

    // ---- Codebook register cache: lane owns k = lane*8..+7, 2 codewords/f32x2.
    u64 cc[4][8];
    {
        const float4* Cm = reinterpret_cast<const float4*>(
            C + ((size_t)m * Kn + (size_t)lane * 8) * Dn);
#pragma unroll
        for (int p = 0; p < 4; p++) {
            float4 a0 = __ldg(Cm + 4 * p + 0);
            float4 a1 = __ldg(Cm + 4 * p + 1);
            float4 b0 = __ldg(Cm + 4 * p + 2);
            float4 b1 = __ldg(Cm + 4 * p + 3);
            cc[p][0] = pack2(a0.x, b0.x); cc[p][1] = pack2(a0.y, b0.y);
            cc[p][2] = pack2(a0.z, b0.z); cc[p][3] = pack2(a0.w, b0.w);
            cc[p][4] = pack2(a1.x, b1.x); cc[p][5] = pack2(a1.y, b1.y);
            cc[p][6] = pack2(a1.z, b1.z); cc[p][7] = pack2(a1.w, b1.w);
        }
    }
    __syncthreads();

    const float* xw    = xsd + warp * RPW * 16;
    const int    brow0 = btile + warp * RPW;
    float* crow = codes + ((size_t)brow0 * Mn + m) * Kn + (size_t)lane * 8;
    const size_t rstride = (size_t)Mn * Kn;

    for (int r = 0; r < RPW; r += 2) {
        float* cpA = crow;
        float* cpB = crow + rstride;

        // Zero stores first: no dependencies, fill the store queue now.
        stg256_zero(cpA);
        stg256_zero(cpB);

        // Dots for the pair (independent chains).
        float fA[8], fB[8];
        row_dots(xw + (r + 0) * 16, cc, fA);
        row_dots(xw + (r + 1) * 16, cc, fB);

        const float bestA = max8(fA);
        const float bestB = max8(fB);
        const u32 oA = ordmap(bestA);
        const u32 oB = ordmap(bestB);
        const u32 mxA = __reduce_max_sync(0xffffffffu, oA);
        const u32 mxB = __reduce_max_sync(0xffffffffu, oB);
        const u32 balA = __ballot_sync(0xffffffffu, oA == mxA);
        const u32 balB = __ballot_sync(0xffffffffu, oB == mxB);

        if (lane == __ffs(balA) - 1)
            emit_owner(fA, bestA, cpA, Cs, lane,
                       xhat + (size_t)(brow0 + r) * FEAT + m * Dn);
        if (lane == __ffs(balB) - 1)
            emit_owner(fB, bestB, cpB, Cs, lane,
                       xhat + (size_t)(brow0 + r + 1) * FEAT + m * Dn);

        crow += 2 * rstride;
    }
}

extern "C" void kernel_launch(void* const* d_in, const int* in_sizes, int n_in,
                              void* d_out, int out_size)
{
    // metadata order: x (B*FEAT), C (M*K*D). Defensive about ordering.
    const float* x = (const float*)d_in[0];
    const float* C = (const float*)d_in[1];
    if (in_sizes[0] == Mn * Kn * Dn && in_sizes[1] == Bn * FEAT) {
        x = (const float*)d_in[1];
        C = (const float*)d_in[0];
    }

    float* xhat  = (float*)d_out;
    float* codes = (float*)d_out + (size_t)Bn * FEAT;

    dim3 grid(Mn, Bn / TILEB);    // (64, 64)
    dim3 block(TILEB);            // 256 threads
    pq_fused_kernel<<<grid, block>>>(x, C, xhat, codes);
}

// round 7
// speedup vs baseline: 1.0146x; 1.0146x over previous
#include <cuda_runtime.h>
#include <math.h>

// PQLayer forward, fully fused (R7 = R4 + store hoist + pipelined argmax):
//   per (b,m): k* = argmax_k <x[b,m*8:+8], C[m,k,:]>
//   codes[b,m,:] = one_hot(k*)   (exact forward value of straight-through)
//   xhat[b,m*8:+8] = C[m,k*,:]
//
// R7 vs R4 (209.3us proven): zero stores issue at iteration top; the
// dots+redux chain for the NEXT row pair runs before the owner patches of the
// CURRENT pair, hiding the serial reduction latency under store issue.
// Dot summation order identical to R3/R4 -> bit-identical argmax.
// (R5's smem-dup x / smem C regressed: extra L1 traffic contends with the
// store wavefronts. Not included.)

#define Bn    16384
#define FEAT  512
#define Mn    64
#define Kn    256
#define Dn    8
#define WARPS 8
#define RPW   32
#define TILEB (WARPS * RPW)   // 256 rows per block

typedef unsigned long long u64;
typedef unsigned int u32;

__device__ __forceinline__ u64 pack2(float lo, float hi) {
    u64 r; asm("mov.b64 %0, {%1,%2};" : "=l"(r) : "f"(lo), "f"(hi)); return r;
}
__device__ __forceinline__ void unpack2(u64 v, float& lo, float& hi) {
    asm("mov.b64 {%0,%1}, %2;" : "=f"(lo), "=f"(hi) : "l"(v));
}
__device__ __forceinline__ u64 fma2(u64 a, u64 b, u64 c) {
    u64 d; asm("fma.rn.f32x2 %0, %1, %2, %3;" : "=l"(d) : "l"(a), "l"(b), "l"(c)); return d;
}
__device__ __forceinline__ u64 mul2(u64 a, u64 b) {
    u64 d; asm("mul.rn.f32x2 %0, %1, %2;" : "=l"(d) : "l"(a), "l"(b)); return d;
}
__device__ __forceinline__ void stg256_zero(void* p) {
    u32 z = 0u;
    asm volatile("st.global.v8.b32 [%0], {%1,%1,%1,%1,%1,%1,%1,%1};"
                 :: "l"(p), "r"(z) : "memory");
}
__device__ __forceinline__ void stg256f(void* p, float4 a, float4 b) {
    asm volatile("st.global.v8.b32 [%0], {%1,%2,%3,%4,%5,%6,%7,%8};"
                 :: "l"(p),
                    "r"(__float_as_uint(a.x)), "r"(__float_as_uint(a.y)),
                    "r"(__float_as_uint(a.z)), "r"(__float_as_uint(a.w)),
                    "r"(__float_as_uint(b.x)), "r"(__float_as_uint(b.y)),
                    "r"(__float_as_uint(b.z)), "r"(__float_as_uint(b.w))
                 : "memory");
}

// Per-row dots + local argmax; order identical to R3/R4.
__device__ __forceinline__ void row_dots(const float* __restrict__ xrow,
                                         const u64 cc[4][8], int lane,
                                         float& best, int& bidx)
{
    const float4 xa = reinterpret_cast<const float4*>(xrow)[0];
    const float4 xb = reinterpret_cast<const float4*>(xrow)[1];
    u64 xx[8] = { pack2(xa.x, xa.x), pack2(xa.y, xa.y),
                  pack2(xa.z, xa.z), pack2(xa.w, xa.w),
                  pack2(xb.x, xb.x), pack2(xb.y, xb.y),
                  pack2(xb.z, xb.z), pack2(xb.w, xb.w) };
    best = -INFINITY;
    bidx = 0;
#pragma unroll
    for (int p = 0; p < 4; p++) {
        u64 acc = mul2(cc[p][0], xx[0]);
#pragma unroll
        for (int d = 1; d < 8; d++) acc = fma2(cc[p][d], xx[d], acc);
        float f0, f1; unpack2(acc, f0, f1);
        const int k0 = lane * 8 + 2 * p;
        if (f0 > best) { best = f0; bidx = k0;     }   // strict >: first-occ
        if (f1 > best) { best = f1; bidx = k0 + 1; }
    }
}

__device__ __forceinline__ int warp_argmax(float best, int bidx)
{
    u32 ord = __float_as_uint(best);
    ord = (ord & 0x80000000u) ? ~ord : (ord | 0x80000000u);
    const u32 mx   = __reduce_max_sync(0xffffffffu, ord);
    const u32 cand = (ord == mx) ? (u32)bidx : 0xFFFFFFFFu;
    return (int)__reduce_min_sync(0xffffffffu, cand);
}

__device__ __forceinline__ void emit_owner(int k, int lane, float* cp,
                                           const float* __restrict__ C,
                                           int m, float* xo)
{
    if ((k >> 3) == lane) {
        cp[k & 7] = 1.0f;      // same thread as the zero store -> ordered
        const float4* cw = reinterpret_cast<const float4*>(
            C + ((size_t)m * Kn + k) * Dn);
        const float4 w0 = __ldg(cw);
        const float4 w1 = __ldg(cw + 1);
        stg256f(xo, w0, w1);
    }
}

__global__ __launch_bounds__(TILEB, 2)
void pq_fused_kernel(const float* __restrict__ x,
                     const float* __restrict__ C,
                     float* __restrict__ xhat,
                     float* __restrict__ codes)
{
    __shared__ float xs[TILEB * Dn];   // 8 KB x tile

    const int m     = blockIdx.x;
    const int warp  = threadIdx.x >> 5;
    const int lane  = threadIdx.x & 31;
    const int tid   = threadIdx.x;
    const int btile = blockIdx.y * TILEB;

    // ---- Stage x tile (coalesced, MLP=16 per warp-instr).
#pragma unroll
    for (int pass = 0; pass < 2; pass++) {
        const int f    = pass * TILEB + tid;
        const int row  = f >> 1;
        const int half = f & 1;
        reinterpret_cast<float4*>(xs)[f] = __ldg(reinterpret_cast<const float4*>(
            x + (size_t)(btile + row) * FEAT + m * Dn + half * 4));
    }

    // ---- Codebook cache: lane owns k = lane*8..+7, two codewords per f32x2.
    u64 cc[4][8];
    {
        const float4* Cm = reinterpret_cast<const float4*>(
            C + ((size_t)m * Kn + (size_t)lane * 8) * Dn);
#pragma unroll
        for (int p = 0; p < 4; p++) {
            float4 a0 = __ldg(Cm + 4 * p + 0);
            float4 a1 = __ldg(Cm + 4 * p + 1);
            float4 b0 = __ldg(Cm + 4 * p + 2);
            float4 b1 = __ldg(Cm + 4 * p + 3);
            cc[p][0] = pack2(a0.x, b0.x); cc[p][1] = pack2(a0.y, b0.y);
            cc[p][2] = pack2(a0.z, b0.z); cc[p][3] = pack2(a0.w, b0.w);
            cc[p][4] = pack2(a1.x, b1.x); cc[p][5] = pack2(a1.y, b1.y);
            cc[p][6] = pack2(a1.z, b1.z); cc[p][7] = pack2(a1.w, b1.w);
        }
    }
    __syncthreads();

    const float* xw    = xs + warp * RPW * Dn;
    const int    brow0 = btile + warp * RPW;
    float* crow = codes + ((size_t)brow0 * Mn + m) * Kn + (size_t)lane * 8;
    const size_t rstride = (size_t)Mn * Kn;

    // ---- Prologue: argmax for rows 0,1.
    int kA, kB;
    {
        float b0v, b1v; int i0, i1;
        row_dots(xw + 0 * Dn, cc, lane, b0v, i0);
        row_dots(xw + 1 * Dn, cc, lane, b1v, i1);
        kA = warp_argmax(b0v, i0);
        kB = warp_argmax(b1v, i1);
    }

    for (int r = 0; r < RPW; r += 2) {
        float* cpA = crow;
        float* cpB = crow + rstride;

        // Zero stores first: operands ready, fill the store queue now.
        stg256_zero(cpA);
        stg256_zero(cpB);

        // Long chain for the NEXT pair overlaps the current pair's stores.
        int kA2 = 0, kB2 = 0;
        if (r + 2 < RPW) {
            float bA2, bB2; int iA2, iB2;
            row_dots(xw + (r + 2) * Dn, cc, lane, bA2, iA2);
            row_dots(xw + (r + 3) * Dn, cc, lane, bB2, iB2);
            kA2 = warp_argmax(bA2, iA2);
            kB2 = warp_argmax(bB2, iB2);
        }

        // Owner patches for the CURRENT pair (kA,kB known since last iter).
        emit_owner(kA, lane, cpA, C, m,
                   xhat + (size_t)(brow0 + r) * FEAT + m * Dn);
        emit_owner(kB, lane, cpB, C, m,
                   xhat + (size_t)(brow0 + r + 1) * FEAT + m * Dn);

        kA = kA2;
        kB = kB2;
        crow += 2 * rstride;
    }
}

extern "C" void kernel_launch(void* const* d_in, const int* in_sizes, int n_in,
                              void* d_out, int out_size)
{
    // metadata order: x (B*FEAT), C (M*K*D). Defensive about ordering.
    const float* x = (const float*)d_in[0];
    const float* C = (const float*)d_in[1];
    if (in_sizes[0] == Mn * Kn * Dn && in_sizes[1] == Bn * FEAT) {
        x = (const float*)d_in[1];
        C = (const float*)d_in[0];
    }

    float* xhat  = (float*)d_out;
    float* codes = (float*)d_out + (size_t)Bn * FEAT;

    dim3 grid(Mn, Bn / TILEB);    // (64, 64)
    dim3 block(TILEB);            // 256 threads
    pq_fused_kernel<<<grid, block>>>(x, C, xhat, codes);
}

// round 10
// speedup vs baseline: 1.0970x; 1.0812x over previous
#include <cuda_runtime.h>
#include <math.h>

// PQLayer forward, fully fused (R8 = R4 body EXACTLY, 64-thread blocks):
//   per (b,m): k* = argmax_k <x[b,m*8:+8], C[m,k,:]>
//   codes[b,m,:] = one_hot(k*)   (exact forward value of straight-through)
//   xhat[b,m*8:+8] = C[m,k*,:]
//
// R8 vs R4 (209.3us proven): ONLY the launch shape changes. 64-thread blocks
// (2 warps) remove the register-quantization waste: 112 regs x 64 thr = 7168
// regs/block -> 9 blocks/SM = 18 warps (vs 16 with 256-thr blocks). Loop body,
// dot order, reduction, and store sequence are byte-identical to R4
// (R5/R7 restructurings of the body both regressed on schedule quality).

#define Bn    16384
#define FEAT  512
#define Mn    64
#define Kn    256
#define Dn    8
#define WARPS 2
#define RPW   32
#define TILEB (WARPS * RPW)   // 64 rows per block

typedef unsigned long long u64;
typedef unsigned int u32;

__device__ __forceinline__ u64 pack2(float lo, float hi) {
    u64 r; asm("mov.b64 %0, {%1,%2};" : "=l"(r) : "f"(lo), "f"(hi)); return r;
}
__device__ __forceinline__ void unpack2(u64 v, float& lo, float& hi) {
    asm("mov.b64 {%0,%1}, %2;" : "=f"(lo), "=f"(hi) : "l"(v));
}
__device__ __forceinline__ u64 fma2(u64 a, u64 b, u64 c) {
    u64 d; asm("fma.rn.f32x2 %0, %1, %2, %3;" : "=l"(d) : "l"(a), "l"(b), "l"(c)); return d;
}
__device__ __forceinline__ u64 mul2(u64 a, u64 b) {
    u64 d; asm("mul.rn.f32x2 %0, %1, %2;" : "=l"(d) : "l"(a), "l"(b)); return d;
}
__device__ __forceinline__ void stg256_zero(void* p) {
    u32 z = 0u;
    asm volatile("st.global.v8.b32 [%0], {%1,%1,%1,%1,%1,%1,%1,%1};"
                 :: "l"(p), "r"(z) : "memory");
}
__device__ __forceinline__ void stg256f(void* p, float4 a, float4 b) {
    asm volatile("st.global.v8.b32 [%0], {%1,%2,%3,%4,%5,%6,%7,%8};"
                 :: "l"(p),
                    "r"(__float_as_uint(a.x)), "r"(__float_as_uint(a.y)),
                    "r"(__float_as_uint(a.z)), "r"(__float_as_uint(a.w)),
                    "r"(__float_as_uint(b.x)), "r"(__float_as_uint(b.y)),
                    "r"(__float_as_uint(b.z)), "r"(__float_as_uint(b.w))
                 : "memory");
}

// Per-row dots + local argmax; order identical to R3/R4.
__device__ __forceinline__ void row_dots(const float* __restrict__ xrow,
                                         const u64 cc[4][8], int lane,
                                         float& best, int& bidx)
{
    const float4 xa = reinterpret_cast<const float4*>(xrow)[0];
    const float4 xb = reinterpret_cast<const float4*>(xrow)[1];
    u64 xx[8] = { pack2(xa.x, xa.x), pack2(xa.y, xa.y),
                  pack2(xa.z, xa.z), pack2(xa.w, xa.w),
                  pack2(xb.x, xb.x), pack2(xb.y, xb.y),
                  pack2(xb.z, xb.z), pack2(xb.w, xb.w) };
    best = -INFINITY;
    bidx = 0;
#pragma unroll
    for (int p = 0; p < 4; p++) {
        u64 acc = mul2(cc[p][0], xx[0]);
#pragma unroll
        for (int d = 1; d < 8; d++) acc = fma2(cc[p][d], xx[d], acc);
        float f0, f1; unpack2(acc, f0, f1);
        const int k0 = lane * 8 + 2 * p;
        if (f0 > best) { best = f0; bidx = k0;     }   // strict >: first-occ
        if (f1 > best) { best = f1; bidx = k0 + 1; }
    }
}

__device__ __forceinline__ int warp_argmax(float best, int bidx)
{
    u32 ord = __float_as_uint(best);
    ord = (ord & 0x80000000u) ? ~ord : (ord | 0x80000000u);
    const u32 mx   = __reduce_max_sync(0xffffffffu, ord);
    const u32 cand = (ord == mx) ? (u32)bidx : 0xFFFFFFFFu;
    return (int)__reduce_min_sync(0xffffffffu, cand);
}

__global__ __launch_bounds__(TILEB, 9)
void pq_fused_kernel(const float* __restrict__ x,
                     const float* __restrict__ C,
                     float* __restrict__ xhat,
                     float* __restrict__ codes)
{
    __shared__ float xs[TILEB * Dn];   // 2 KB x tile

    const int m     = blockIdx.x;
    const int warp  = threadIdx.x >> 5;
    const int lane  = threadIdx.x & 31;
    const int tid   = threadIdx.x;
    const int btile = blockIdx.y * TILEB;

    // ---- Stage x tile (coalesced, MLP=16 per warp-instr).
#pragma unroll
    for (int pass = 0; pass < 2; pass++) {
        const int f    = pass * TILEB + tid;
        const int row  = f >> 1;
        const int half = f & 1;
        reinterpret_cast<float4*>(xs)[f] = __ldg(reinterpret_cast<const float4*>(
            x + (size_t)(btile + row) * FEAT + m * Dn + half * 4));
    }

    // ---- Codebook cache: lane owns k = lane*8..+7, two codewords per f32x2.
    u64 cc[4][8];
    {
        const float4* Cm = reinterpret_cast<const float4*>(
            C + ((size_t)m * Kn + (size_t)lane * 8) * Dn);
#pragma unroll
        for (int p = 0; p < 4; p++) {
            float4 a0 = __ldg(Cm + 4 * p + 0);
            float4 a1 = __ldg(Cm + 4 * p + 1);
            float4 b0 = __ldg(Cm + 4 * p + 2);
            float4 b1 = __ldg(Cm + 4 * p + 3);
            cc[p][0] = pack2(a0.x, b0.x); cc[p][1] = pack2(a0.y, b0.y);
            cc[p][2] = pack2(a0.z, b0.z); cc[p][3] = pack2(a0.w, b0.w);
            cc[p][4] = pack2(a1.x, b1.x); cc[p][5] = pack2(a1.y, b1.y);
            cc[p][6] = pack2(a1.z, b1.z); cc[p][7] = pack2(a1.w, b1.w);
        }
    }
    __syncthreads();

    const float* xw    = xs + warp * RPW * Dn;
    const int    brow0 = btile + warp * RPW;
    float* crow = codes + ((size_t)brow0 * Mn + m) * Kn + (size_t)lane * 8;
    const size_t rstride = (size_t)Mn * Kn;

    for (int r = 0; r < RPW; r += 2) {
        // --- dots for the row pair (independent chains, compiler interleaves)
        float bestA, bestB; int idxA, idxB;
        row_dots(xw + (r + 0) * Dn, cc, lane, bestA, idxA);
        row_dots(xw + (r + 1) * Dn, cc, lane, bestB, idxB);

        // --- the two redux chains overlap their latency
        const int kA = warp_argmax(bestA, idxA);
        const int kB = warp_argmax(bestB, idxB);

        // --- stores, row A
        {
            const int b = brow0 + r;
            float* cp = crow;
            stg256_zero(cp);
            if ((kA >> 3) == lane) {
                // patch the 1.0 (same thread as the zero store -> ordered)
                *(cp + (kA & 7)) = 1.0f;
                const float4* cw = reinterpret_cast<const float4*>(
                    C + ((size_t)m * Kn + kA) * Dn);
                const float4 w0 = __ldg(cw);
                const float4 w1 = __ldg(cw + 1);
                stg256f(xhat + (size_t)b * FEAT + m * Dn, w0, w1);
            }
        }
        // --- stores, row B
        {
            const int b = brow0 + r + 1;
            float* cp = crow + rstride;
            stg256_zero(cp);
            if ((kB >> 3) == lane) {
                *(cp + (kB & 7)) = 1.0f;
                const float4* cw = reinterpret_cast<const float4*>(
                    C + ((size_t)m * Kn + kB) * Dn);
                const float4 w0 = __ldg(cw);
                const float4 w1 = __ldg(cw + 1);
                stg256f(xhat + (size_t)b * FEAT + m * Dn, w0, w1);
            }
        }
        crow += 2 * rstride;
    }
}

extern "C" void kernel_launch(void* const* d_in, const int* in_sizes, int n_in,
                              void* d_out, int out_size)
{
    // metadata order: x (B*FEAT), C (M*K*D). Defensive about ordering.
    const float* x = (const float*)d_in[0];
    const float* C = (const float*)d_in[1];
    if (in_sizes[0] == Mn * Kn * Dn && in_sizes[1] == Bn * FEAT) {
        x = (const float*)d_in[1];
        C = (const float*)d_in[0];
    }

    float* xhat  = (float*)d_out;
    float* codes = (float*)d_out + (size_t)Bn * FEAT;

    dim3 grid(Mn, Bn / TILEB);    // (64, 256)
    dim3 block(TILEB);            // 64 threads (2 warps)
    pq_fused_kernel<<<grid, block>>>(x, C, xhat, codes);
}

// round 11
// speedup vs baseline: 1.1104x; 1.0122x over previous
#include <cuda_runtime.h>
#include <math.h>

// PQLayer forward, fully fused (R11 = R8 body EXACTLY, 10 blocks/SM):
//   per (b,m): k* = argmax_k <x[b,m*8:+8], C[m,k,:]>
//   codes[b,m,:] = one_hot(k*)   (exact forward value of straight-through)
//   xhat[b,m*8:+8] = C[m,k*,:]
//
// R11 vs R8 (209.15us proven): ONLY the residency cap changes. R8 compiled to
// 96 regs at 64-thr blocks, so 10 blocks/SM fit (10*64*96 = 61440 <= 65536);
// the old __launch_bounds__(64,9) capped us at 18 warps. Now 20 warps/SM.
// Loop body, dot order, reduction, store sequence byte-identical to R4/R8.

#define Bn    16384
#define FEAT  512
#define Mn    64
#define Kn    256
#define Dn    8
#define WARPS 2
#define RPW   32
#define TILEB (WARPS * RPW)   // 64 rows per block

typedef unsigned long long u64;
typedef unsigned int u32;

__device__ __forceinline__ u64 pack2(float lo, float hi) {
    u64 r; asm("mov.b64 %0, {%1,%2};" : "=l"(r) : "f"(lo), "f"(hi)); return r;
}
__device__ __forceinline__ void unpack2(u64 v, float& lo, float& hi) {
    asm("mov.b64 {%0,%1}, %2;" : "=f"(lo), "=f"(hi) : "l"(v));
}
__device__ __forceinline__ u64 fma2(u64 a, u64 b, u64 c) {
    u64 d; asm("fma.rn.f32x2 %0, %1, %2, %3;" : "=l"(d) : "l"(a), "l"(b), "l"(c)); return d;
}
__device__ __forceinline__ u64 mul2(u64 a, u64 b) {
    u64 d; asm("mul.rn.f32x2 %0, %1, %2;" : "=l"(d) : "l"(a), "l"(b)); return d;
}
__device__ __forceinline__ void stg256_zero(void* p) {
    u32 z = 0u;
    asm volatile("st.global.v8.b32 [%0], {%1,%1,%1,%1,%1,%1,%1,%1};"
                 :: "l"(p), "r"(z) : "memory");
}
__device__ __forceinline__ void stg256f(void* p, float4 a, float4 b) {
    asm volatile("st.global.v8.b32 [%0], {%1,%2,%3,%4,%5,%6,%7,%8};"
                 :: "l"(p),
                    "r"(__float_as_uint(a.x)), "r"(__float_as_uint(a.y)),
                    "r"(__float_as_uint(a.z)), "r"(__float_as_uint(a.w)),
                    "r"(__float_as_uint(b.x)), "r"(__float_as_uint(b.y)),
                    "r"(__float_as_uint(b.z)), "r"(__float_as_uint(b.w))
                 : "memory");
}

// Per-row dots + local argmax; order identical to R3/R4.
__device__ __forceinline__ void row_dots(const float* __restrict__ xrow,
                                         const u64 cc[4][8], int lane,
                                         float& best, int& bidx)
{
    const float4 xa = reinterpret_cast<const float4*>(xrow)[0];
    const float4 xb = reinterpret_cast<const float4*>(xrow)[1];
    u64 xx[8] = { pack2(xa.x, xa.x), pack2(xa.y, xa.y),
                  pack2(xa.z, xa.z), pack2(xa.w, xa.w),
                  pack2(xb.x, xb.x), pack2(xb.y, xb.y),
                  pack2(xb.z, xb.z), pack2(xb.w, xb.w) };
    best = -INFINITY;
    bidx = 0;
#pragma unroll
    for (int p = 0; p < 4; p++) {
        u64 acc = mul2(cc[p][0], xx[0]);
#pragma unroll
        for (int d = 1; d < 8; d++) acc = fma2(cc[p][d], xx[d], acc);
        float f0, f1; unpack2(acc, f0, f1);
        const int k0 = lane * 8 + 2 * p;
        if (f0 > best) { best = f0; bidx = k0;     }   // strict >: first-occ
        if (f1 > best) { best = f1; bidx = k0 + 1; }
    }
}

__device__ __forceinline__ int warp_argmax(float best, int bidx)
{
    u32 ord = __float_as_uint(best);
    ord = (ord & 0x80000000u) ? ~ord : (ord | 0x80000000u);
    const u32 mx   = __reduce_max_sync(0xffffffffu, ord);
    const u32 cand = (ord == mx) ? (u32)bidx : 0xFFFFFFFFu;
    return (int)__reduce_min_sync(0xffffffffu, cand);
}

__global__ __launch_bounds__(TILEB, 10)
void pq_fused_kernel(const float* __restrict__ x,
                     const float* __restrict__ C,
                     float* __restrict__ xhat,
                     float* __restrict__ codes)
{
    __shared__ float xs[TILEB * Dn];   // 2 KB x tile

    const int m     = blockIdx.x;
    const int warp  = threadIdx.x >> 5;
    const int lane  = threadIdx.x & 31;
    const int tid   = threadIdx.x;
    const int btile = blockIdx.y * TILEB;

    // ---- Stage x tile (coalesced, MLP=16 per warp-instr).
#pragma unroll
    for (int pass = 0; pass < 2; pass++) {
        const int f    = pass * TILEB + tid;
        const int row  = f >> 1;
        const int half = f & 1;
        reinterpret_cast<float4*>(xs)[f] = __ldg(reinterpret_cast<const float4*>(
            x + (size_t)(btile + row) * FEAT + m * Dn + half * 4));
    }

    // ---- Codebook cache: lane owns k = lane*8..+7, two codewords per f32x2.
    u64 cc[4][8];
    {
        const float4* Cm = reinterpret_cast<const float4*>(
            C + ((size_t)m * Kn + (size_t)lane * 8) * Dn);
#pragma unroll
        for (int p = 0; p < 4; p++) {
            float4 a0 = __ldg(Cm + 4 * p + 0);
            float4 a1 = __ldg(Cm + 4 * p + 1);
            float4 b0 = __ldg(Cm + 4 * p + 2);
            float4 b1 = __ldg(Cm + 4 * p + 3);
            cc[p][0] = pack2(a0.x, b0.x); cc[p][1] = pack2(a0.y, b0.y);
            cc[p][2] = pack2(a0.z, b0.z); cc[p][3] = pack2(a0.w, b0.w);
            cc[p][4] = pack2(a1.x, b1.x); cc[p][5] = pack2(a1.y, b1.y);
            cc[p][6] = pack2(a1.z, b1.z); cc[p][7] = pack2(a1.w, b1.w);
        }
    }
    __syncthreads();

    const float* xw    = xs + warp * RPW * Dn;
    const int    brow0 = btile + warp * RPW;
    float* crow = codes + ((size_t)brow0 * Mn + m) * Kn + (size_t)lane * 8;
    const size_t rstride = (size_t)Mn * Kn;

    for (int r = 0; r < RPW; r += 2) {
        // --- dots for the row pair (independent chains, compiler interleaves)
        float bestA, bestB; int idxA, idxB;
        row_dots(xw + (r + 0) * Dn, cc, lane, bestA, idxA);
        row_dots(xw + (r + 1) * Dn, cc, lane, bestB, idxB);

        // --- the two redux chains overlap their latency
        const int kA = warp_argmax(bestA, idxA);
        const int kB = warp_argmax(bestB, idxB);

        // --- stores, row A
        {
            const int b = brow0 + r;
            float* cp = crow;
            stg256_zero(cp);
            if ((kA >> 3) == lane) {
                // patch the 1.0 (same thread as the zero store -> ordered)
                *(cp + (kA & 7)) = 1.0f;
                const float4* cw = reinterpret_cast<const float4*>(
                    C + ((size_t)m * Kn + kA) * Dn);
                const float4 w0 = __ldg(cw);
                const float4 w1 = __ldg(cw + 1);
                stg256f(xhat + (size_t)b * FEAT + m * Dn, w0, w1);
            }
        }
        // --- stores, row B
        {
            const int b = brow0 + r + 1;
            float* cp = crow + rstride;
            stg256_zero(cp);
            if ((kB >> 3) == lane) {
                *(cp + (kB & 7)) = 1.0f;
                const float4* cw = reinterpret_cast<const float4*>(
                    C + ((size_t)m * Kn + kB) * Dn);
                const float4 w0 = __ldg(cw);
                const float4 w1 = __ldg(cw + 1);
                stg256f(xhat + (size_t)b * FEAT + m * Dn, w0, w1);
            }
        }
        crow += 2 * rstride;
    }
}

extern "C" void kernel_launch(void* const* d_in, const int* in_sizes, int n_in,
                              void* d_out, int out_size)
{
    // metadata order: x (B*FEAT), C (M*K*D). Defensive about ordering.
    const float* x = (const float*)d_in[0];
    const float* C = (const float*)d_in[1];
    if (in_sizes[0] == Mn * Kn * Dn && in_sizes[1] == Bn * FEAT) {
        x = (const float*)d_in[1];
        C = (const float*)d_in[0];
    }

    float* xhat  = (float*)d_out;
    float* codes = (float*)d_out + (size_t)Bn * FEAT;

    dim3 grid(Mn, Bn / TILEB);    // (64, 256)
    dim3 block(TILEB);            // 64 threads (2 warps)
    pq_fused_kernel<<<grid, block>>>(x, C, xhat, codes);
}